// round 9
// baseline (speedup 1.0000x reference)
#include <cuda_runtime.h>
#include <cstdint>

#define HW_ (128*128)
#define NTOT (16*64)

__device__ float g_Q[NTOT * HW_];
__device__ float g_V[NTOT * HW_];
__device__ float g_K[NTOT * HW_];

__device__ __forceinline__ void mma_tf32(float c[4], const uint32_t a[4],
                                         const uint32_t b0, const uint32_t b1) {
    asm volatile(
        "mma.sync.aligned.m16n8k8.row.col.f32.tf32.tf32.f32 "
        "{%0,%1,%2,%3}, {%4,%5,%6,%7}, {%8,%9}, {%0,%1,%2,%3};"
        : "+f"(c[0]), "+f"(c[1]), "+f"(c[2]), "+f"(c[3])
        : "r"(a[0]), "r"(a[1]), "r"(a[2]), "r"(a[3]), "r"(b0), "r"(b1));
}

__device__ __forceinline__ void tf32_split(float x, uint32_t& hi, uint32_t& lo) {
    hi = __float_as_uint(x) & 0xffffe000u;
    float r = x - __uint_as_float(hi);
    lo = __float_as_uint(r) & 0xffffe000u;
}

// ---------------------------------------------------------------------------
// Kernel 1: fused 1x1-conv projections, tensor cores, smem-staged inputs.
// 512 thr / 16 warps. Warp (wb, wh): pixel sub-tile wb*16, channel half wh*32.
// X/E tiles staged in smem with stride 136 (conflict-free fragment loads).
// ---------------------------------------------------------------------------
#define LDX 136

__global__ __launch_bounds__(512) void qvk_kernel(
    const float* __restrict__ x, const float* __restrict__ e,
    const float* __restrict__ W1, const float* __restrict__ b1,
    const float* __restrict__ W2, const float* __restrict__ b2,
    const float* __restrict__ W3, const float* __restrict__ b3)
{
    extern __shared__ float sm[];
    float* W2h = sm;                 // [64][68]
    float* W2l = W2h + 64*68;
    float* W3h = W2l + 64*68;
    float* W3l = W3h + 64*68;
    float* W1h = W3l + 64*68;        // [64][20]
    float* W1l = W1h + 64*20;
    float* b1s = W1l + 64*20;
    float* b2s = b1s + 64;
    float* b3s = b2s + 64;
    float* Xs  = b3s + 64;           // [64][136]
    float* Es  = Xs + 64*LDX;        // [16][136]

    const int tid = threadIdx.x;
    const int b   = blockIdx.y;
    const int pblk = blockIdx.x * 128;

    for (int idx = tid; idx < 4096; idx += 512) {
        int o = idx >> 6, c = idx & 63;
        uint32_t hi, lo;
        tf32_split(W2[idx], hi, lo);
        W2h[o*68 + c] = __uint_as_float(hi);
        W2l[o*68 + c] = __uint_as_float(lo);
        tf32_split(W3[idx], hi, lo);
        W3h[o*68 + c] = __uint_as_float(hi);
        W3l[o*68 + c] = __uint_as_float(lo);
    }
    for (int idx = tid; idx < 1024; idx += 512) {
        int o = idx >> 4, c = idx & 15;
        uint32_t hi, lo;
        tf32_split(W1[idx], hi, lo);
        W1h[o*20 + c] = __uint_as_float(hi);
        W1l[o*20 + c] = __uint_as_float(lo);
    }
    if (tid < 64) { b1s[tid] = b1[tid]; b2s[tid] = b2[tid]; b3s[tid] = b3[tid]; }

    // Stage X (64x128) and E (16x128) tiles, coalesced float4
    const float* xb = x + b*64*HW_ + pblk;
    const float* eb = e + b*16*HW_ + pblk;
    for (int idx = tid; idx < 64*32; idx += 512) {
        int c = idx >> 5, c4 = (idx & 31) * 4;
        *(float4*)&Xs[c*LDX + c4] = *(const float4*)&xb[c*HW_ + c4];
    }
    for (int idx = tid; idx < 16*32; idx += 512) {
        int c = idx >> 5, c4 = (idx & 31) * 4;
        *(float4*)&Es[c*LDX + c4] = *(const float4*)&eb[c*HW_ + c4];
    }
    __syncthreads();

    const int warp = tid >> 5;
    const int lane = tid & 31;
    const int g4 = lane >> 2;
    const int tg = lane & 3;
    const int wb = warp & 7;
    const int wh = warp >> 3;
    const int p0 = wb*16;        // pixel offset within tile
    const int o0 = wh*32;

    float accV[2][2][4], accK[2][2][4], accQ[2][2][4];
    #pragma unroll
    for (int mt = 0; mt < 2; mt++) {
        int r = o0 + mt*16 + g4;
        float v0 = b2s[r], v1 = b2s[r+8];
        float k0 = b3s[r], k1 = b3s[r+8];
        float q0 = b1s[r], q1 = b1s[r+8];
        #pragma unroll
        for (int ntl = 0; ntl < 2; ntl++) {
            accV[mt][ntl][0] = v0; accV[mt][ntl][1] = v0;
            accV[mt][ntl][2] = v1; accV[mt][ntl][3] = v1;
            accK[mt][ntl][0] = k0; accK[mt][ntl][1] = k0;
            accK[mt][ntl][2] = k1; accK[mt][ntl][3] = k1;
            accQ[mt][ntl][0] = q0; accQ[mt][ntl][1] = q0;
            accQ[mt][ntl][2] = q1; accQ[mt][ntl][3] = q1;
        }
    }

    // ---- V, K over C=64 (X b-fragments from smem, shared by V & K)
    #pragma unroll 2
    for (int ks = 0; ks < 8; ks++) {
        const int c0 = ks*8;
        uint32_t bh[2][2], bl[2][2];
        #pragma unroll
        for (int ntl = 0; ntl < 2; ntl++) {
            int pcol = p0 + ntl*8 + g4;
            tf32_split(Xs[(c0+tg)*LDX + pcol],   bh[ntl][0], bl[ntl][0]);
            tf32_split(Xs[(c0+tg+4)*LDX + pcol], bh[ntl][1], bl[ntl][1]);
        }
        #pragma unroll
        for (int mt = 0; mt < 2; mt++) {
            const int rb = (o0 + mt*16 + g4)*68 + c0 + tg;
            uint32_t ah[4], al[4];
            ah[0] = __float_as_uint(W2h[rb]);
            ah[1] = __float_as_uint(W2h[rb + 8*68]);
            ah[2] = __float_as_uint(W2h[rb + 4]);
            ah[3] = __float_as_uint(W2h[rb + 8*68 + 4]);
            al[0] = __float_as_uint(W2l[rb]);
            al[1] = __float_as_uint(W2l[rb + 8*68]);
            al[2] = __float_as_uint(W2l[rb + 4]);
            al[3] = __float_as_uint(W2l[rb + 8*68 + 4]);
            #pragma unroll
            for (int ntl = 0; ntl < 2; ntl++) {
                mma_tf32(accV[mt][ntl], ah, bh[ntl][0], bh[ntl][1]);
                mma_tf32(accV[mt][ntl], al, bh[ntl][0], bh[ntl][1]);
                mma_tf32(accV[mt][ntl], ah, bl[ntl][0], bl[ntl][1]);
            }
            ah[0] = __float_as_uint(W3h[rb]);
            ah[1] = __float_as_uint(W3h[rb + 8*68]);
            ah[2] = __float_as_uint(W3h[rb + 4]);
            ah[3] = __float_as_uint(W3h[rb + 8*68 + 4]);
            al[0] = __float_as_uint(W3l[rb]);
            al[1] = __float_as_uint(W3l[rb + 8*68]);
            al[2] = __float_as_uint(W3l[rb + 4]);
            al[3] = __float_as_uint(W3l[rb + 8*68 + 4]);
            #pragma unroll
            for (int ntl = 0; ntl < 2; ntl++) {
                mma_tf32(accK[mt][ntl], ah, bh[ntl][0], bh[ntl][1]);
                mma_tf32(accK[mt][ntl], al, bh[ntl][0], bh[ntl][1]);
                mma_tf32(accK[mt][ntl], ah, bl[ntl][0], bl[ntl][1]);
            }
        }
    }

    // ---- Q over C1=16 (E b-fragments from smem)
    #pragma unroll
    for (int ks = 0; ks < 2; ks++) {
        const int c0 = ks*8;
        uint32_t bh[2][2], bl[2][2];
        #pragma unroll
        for (int ntl = 0; ntl < 2; ntl++) {
            int pcol = p0 + ntl*8 + g4;
            tf32_split(Es[(c0+tg)*LDX + pcol],   bh[ntl][0], bl[ntl][0]);
            tf32_split(Es[(c0+tg+4)*LDX + pcol], bh[ntl][1], bl[ntl][1]);
        }
        #pragma unroll
        for (int mt = 0; mt < 2; mt++) {
            const int rb = (o0 + mt*16 + g4)*20 + c0 + tg;
            uint32_t ah[4], al[4];
            ah[0] = __float_as_uint(W1h[rb]);
            ah[1] = __float_as_uint(W1h[rb + 8*20]);
            ah[2] = __float_as_uint(W1h[rb + 4]);
            ah[3] = __float_as_uint(W1h[rb + 8*20 + 4]);
            al[0] = __float_as_uint(W1l[rb]);
            al[1] = __float_as_uint(W1l[rb + 8*20]);
            al[2] = __float_as_uint(W1l[rb + 4]);
            al[3] = __float_as_uint(W1l[rb + 8*20 + 4]);
            #pragma unroll
            for (int ntl = 0; ntl < 2; ntl++) {
                mma_tf32(accQ[mt][ntl], ah, bh[ntl][0], bh[ntl][1]);
                mma_tf32(accQ[mt][ntl], al, bh[ntl][0], bh[ntl][1]);
                mma_tf32(accQ[mt][ntl], ah, bl[ntl][0], bl[ntl][1]);
            }
        }
    }

    // ---- Store
    #pragma unroll
    for (int mt = 0; mt < 2; mt++) {
        int r = o0 + mt*16 + g4;
        #pragma unroll
        for (int ntl = 0; ntl < 2; ntl++) {
            int pc = pblk + p0 + ntl*8 + 2*tg;
            int i0 = (b*64 + r)*HW_ + pc;
            int i1 = (b*64 + r + 8)*HW_ + pc;
            *(float2*)&g_V[i0] = make_float2(accV[mt][ntl][0], accV[mt][ntl][1]);
            *(float2*)&g_V[i1] = make_float2(accV[mt][ntl][2], accV[mt][ntl][3]);
            *(float2*)&g_K[i0] = make_float2(accK[mt][ntl][0], accK[mt][ntl][1]);
            *(float2*)&g_K[i1] = make_float2(accK[mt][ntl][2], accK[mt][ntl][3]);
            *(float2*)&g_Q[i0] = make_float2(accQ[mt][ntl][0], accQ[mt][ntl][1]);
            *(float2*)&g_Q[i1] = make_float2(accQ[mt][ntl][2], accQ[mt][ntl][3]);
        }
    }
}

// ---------------------------------------------------------------------------
// Kernel 2: per-head attention on tensor cores, 1024 threads (R8 winner).
// ---------------------------------------------------------------------------
#define LDA 132

__global__ __launch_bounds__(1024) void attn_kernel(float* __restrict__ out)
{
    extern __shared__ float sm[];
    float* A    = sm;
    float* Bm   = sm + 128*LDA;
    float* redM = sm + 2*128*LDA;  // [4][128]
    float* redS = redM + 4*128;    // [4][128]

    const int tid  = threadIdx.x;
    const int warp = tid >> 5;
    const int lane = tid & 31;
    const int wb   = warp & 7;
    const int wq   = warp >> 3;
    const int n    = blockIdx.x;
    const float* Q = g_Q + n*HW_;
    const float* V = g_V + n*HW_;
    const float* K = g_K + n*HW_;

    for (int idx = tid; idx < 128*32; idx += 1024) {
        int row = idx >> 5, c4 = (idx & 31) * 4;
        *(float4*)&A[row*LDA + c4]  = *(const float4*)&Q[row*128 + c4];
        *(float4*)&Bm[row*LDA + c4] = *(const float4*)&V[row*128 + c4];
    }
    __syncthreads();

    const int g4 = lane >> 2;
    const int tg = lane & 3;
    const int r0 = wb*16 + g4;
    const int nt0 = wq*4;

    float acc[4][4];
    #pragma unroll
    for (int j = 0; j < 4; j++)
        #pragma unroll
        for (int i = 0; i < 4; i++) acc[j][i] = 0.0f;

    #pragma unroll 1
    for (int k = 0; k < 16; k++) {
        const int kb = k*8 + tg;
        uint32_t ah[4], al[4];
        tf32_split(A[r0*LDA + kb],         ah[0], al[0]);
        tf32_split(A[(r0+8)*LDA + kb],     ah[1], al[1]);
        tf32_split(A[r0*LDA + kb + 4],     ah[2], al[2]);
        tf32_split(A[(r0+8)*LDA + kb + 4], ah[3], al[3]);
        #pragma unroll
        for (int j = 0; j < 4; j++) {
            const int gc = (nt0 + j)*8 + g4;
            uint32_t bh0, bl0, bh1, bl1;
            tf32_split(Bm[gc*LDA + kb],     bh0, bl0);
            tf32_split(Bm[gc*LDA + kb + 4], bh1, bl1);
            mma_tf32(acc[j], ah, bh0, bh1);
            mma_tf32(acc[j], al, bh0, bh1);
            mma_tf32(acc[j], ah, bl0, bl1);
        }
    }

    float m1 = -1e30f, m2 = -1e30f;
    #pragma unroll
    for (int j = 0; j < 4; j++) {
        m1 = fmaxf(m1, fmaxf(acc[j][0], acc[j][1]));
        m2 = fmaxf(m2, fmaxf(acc[j][2], acc[j][3]));
    }
    #pragma unroll
    for (int off = 1; off < 4; off <<= 1) {
        m1 = fmaxf(m1, __shfl_xor_sync(0xFFFFFFFFu, m1, off));
        m2 = fmaxf(m2, __shfl_xor_sync(0xFFFFFFFFu, m2, off));
    }
    if (tg == 0) {
        redM[wq*128 + r0]     = m1;
        redM[wq*128 + r0 + 8] = m2;
    }
    __syncthreads();

    const float gm1 = fmaxf(fmaxf(redM[r0],       redM[128 + r0]),
                            fmaxf(redM[256 + r0], redM[384 + r0]));
    const float gm2 = fmaxf(fmaxf(redM[r0+8],       redM[128 + r0+8]),
                            fmaxf(redM[256 + r0+8], redM[384 + r0+8]));

    float s1 = 0.0f, s2 = 0.0f;
    #pragma unroll
    for (int j = 0; j < 4; j++) {
        acc[j][0] = __expf(acc[j][0] - gm1);
        acc[j][1] = __expf(acc[j][1] - gm1);
        acc[j][2] = __expf(acc[j][2] - gm2);
        acc[j][3] = __expf(acc[j][3] - gm2);
        s1 += acc[j][0] + acc[j][1];
        s2 += acc[j][2] + acc[j][3];
    }
    #pragma unroll
    for (int off = 1; off < 4; off <<= 1) {
        s1 += __shfl_xor_sync(0xFFFFFFFFu, s1, off);
        s2 += __shfl_xor_sync(0xFFFFFFFFu, s2, off);
    }
    if (tg == 0) {
        redS[wq*128 + r0]     = s1;
        redS[wq*128 + r0 + 8] = s2;
    }

    #pragma unroll
    for (int j = 0; j < 4; j++) {
        const int cb = (nt0 + j)*8 + 2*tg;
        *(float2*)&A[r0*LDA     + cb] = make_float2(acc[j][0], acc[j][1]);
        *(float2*)&A[(r0+8)*LDA + cb] = make_float2(acc[j][2], acc[j][3]);
    }
    for (int idx = tid; idx < 128*32; idx += 1024) {
        int row = idx >> 5, c4 = (idx & 31) * 4;
        *(float4*)&Bm[row*LDA + c4] = *(const float4*)&K[row*128 + c4];
    }
    __syncthreads();

    const float inv1 = 1.0f / (redS[r0] + redS[128 + r0] +
                               redS[256 + r0] + redS[384 + r0]);
    const float inv2 = 1.0f / (redS[r0+8] + redS[128 + r0+8] +
                               redS[256 + r0+8] + redS[384 + r0+8]);

    float oac[4][4];
    #pragma unroll
    for (int j = 0; j < 4; j++)
        #pragma unroll
        for (int i = 0; i < 4; i++) oac[j][i] = 0.0f;

    #pragma unroll 1
    for (int k = 0; k < 16; k++) {
        const int kb = k*8 + tg;
        uint32_t ah[4], al[4];
        tf32_split(A[r0*LDA + kb],         ah[0], al[0]);
        tf32_split(A[(r0+8)*LDA + kb],     ah[1], al[1]);
        tf32_split(A[r0*LDA + kb + 4],     ah[2], al[2]);
        tf32_split(A[(r0+8)*LDA + kb + 4], ah[3], al[3]);
        #pragma unroll
        for (int j = 0; j < 4; j++) {
            const int nc = (nt0 + j)*8 + g4;
            uint32_t bh0, bl0, bh1, bl1;
            tf32_split(Bm[kb*LDA + nc],     bh0, bl0);
            tf32_split(Bm[(kb+4)*LDA + nc], bh1, bl1);
            mma_tf32(oac[j], ah, bh0, bh1);
            mma_tf32(oac[j], al, bh0, bh1);
            mma_tf32(oac[j], ah, bl0, bl1);
        }
    }

    #pragma unroll
    for (int j = 0; j < 4; j++) {
        const int cb = (nt0 + j)*8 + 2*tg;
        *(float2*)&out[n*HW_ + r0*128 + cb] =
            make_float2(oac[j][0]*inv1, oac[j][1]*inv1);
        *(float2*)&out[n*HW_ + (r0+8)*128 + cb] =
            make_float2(oac[j][2]*inv2, oac[j][3]*inv2);
    }
}

// ---------------------------------------------------------------------------
extern "C" void kernel_launch(void* const* d_in, const int* in_sizes, int n_in,
                              void* d_out, int out_size)
{
    const float* x  = (const float*)d_in[0];
    const float* e  = (const float*)d_in[1];
    const float* W1 = (const float*)d_in[2];
    const float* b1 = (const float*)d_in[3];
    const float* W2 = (const float*)d_in[4];
    const float* b2 = (const float*)d_in[5];
    const float* W3 = (const float*)d_in[6];
    const float* b3 = (const float*)d_in[7];
    float* out = (float*)d_out;

    const int smem1 = (4*64*68 + 2*64*20 + 3*64 + 64*LDX + 16*LDX) * (int)sizeof(float);
    cudaFuncSetAttribute(qvk_kernel, cudaFuncAttributeMaxDynamicSharedMemorySize, smem1);
    qvk_kernel<<<dim3(128, 16), 512, smem1>>>(x, e, W1, b1, W2, b2, W3, b3);

    const int smem2 = (2*128*LDA + 8*128) * (int)sizeof(float);
    cudaFuncSetAttribute(attn_kernel, cudaFuncAttributeMaxDynamicSharedMemorySize, smem2);
    attn_kernel<<<NTOT, 1024, smem2>>>(out);
}